// round 1
// baseline (speedup 1.0000x reference)
#include <cuda_runtime.h>
#include <math.h>

#define L_DIM 2048
#define N_DIM 4
#define E_DIM 1024
#define H_DIM 8
#define M1    (L_DIM * N_DIM)   // 8192 rows (l,n)
#define F3    (3 * E_DIM)       // 3072

// ------------------------------------------------------------------
// Scratch (allocation-free: __device__ globals)
// ------------------------------------------------------------------
__device__ float g_qkv[(long)H_DIM * M1 * F3];                    // [h][m=(l*N+n)][f]   805 MB
__device__ float g_scores[(long)H_DIM * N_DIM * L_DIM * L_DIM];   // [h][n][i][j]        537 MB (softmax in place)
__device__ float g_ctx[(long)H_DIM * M1 * E_DIM];                 // [h][m][e]           268 MB

// ------------------------------------------------------------------
// Tiled SGEMM core: 128x128 block, 16 k-slice, 8x8 per thread, 256 thr
// C[m,n] += sum_k A[m*lda + k] * (BT ? B[n*ldb + k] : B[k*ldb + n])
// A is pre-offset to the block's row origin; B to its col origin.
// All dims here are multiples of the tile sizes -> no bounds checks.
// ------------------------------------------------------------------
#define BM 128
#define BN 128
#define BK 16
#define TM 8
#define TN 8
#define NTHR 256

struct Smem {
    float As[BK][BM + 4];
    float Bs[BK][BN + 4];
};

template <bool BT>
__device__ __forceinline__ void gemm_core(const float* __restrict__ A, long lda,
                                          const float* __restrict__ B, long ldb,
                                          int K, Smem& s, float acc[TM][TN]) {
    const int tid = threadIdx.x;
    for (int k0 = 0; k0 < K; k0 += BK) {
        // --- load A tile (transpose into As[k][m]) ---
        #pragma unroll
        for (int i = 0; i < 2; i++) {
            int idx = tid + i * NTHR;          // 0..511
            int m   = idx >> 2;                // 0..127
            int kq  = (idx & 3) << 2;          // 0,4,8,12
            float4 v = *reinterpret_cast<const float4*>(&A[(long)m * lda + k0 + kq]);
            s.As[kq + 0][m] = v.x;
            s.As[kq + 1][m] = v.y;
            s.As[kq + 2][m] = v.z;
            s.As[kq + 3][m] = v.w;
        }
        // --- load B tile ---
        if (BT) {
            #pragma unroll
            for (int i = 0; i < 2; i++) {
                int idx = tid + i * NTHR;
                int n   = idx >> 2;
                int kq  = (idx & 3) << 2;
                float4 v = *reinterpret_cast<const float4*>(&B[(long)n * ldb + k0 + kq]);
                s.Bs[kq + 0][n] = v.x;
                s.Bs[kq + 1][n] = v.y;
                s.Bs[kq + 2][n] = v.z;
                s.Bs[kq + 3][n] = v.w;
            }
        } else {
            #pragma unroll
            for (int i = 0; i < 2; i++) {
                int idx = tid + i * NTHR;
                int k   = idx >> 5;            // 0..15
                int n   = (idx & 31) << 2;     // 0..124
                float4 v = *reinterpret_cast<const float4*>(&B[(long)(k0 + k) * ldb + n]);
                *reinterpret_cast<float4*>(&s.Bs[k][n]) = v;
            }
        }
        __syncthreads();
        // --- compute ---
        const int tx = tid & 15;
        const int ty = tid >> 4;
        #pragma unroll
        for (int k = 0; k < BK; k++) {
            float a[TM], b[TN];
            #pragma unroll
            for (int i = 0; i < TM; i++) a[i] = s.As[k][ty * TM + i];
            #pragma unroll
            for (int j = 0; j < TN; j++) b[j] = s.Bs[k][tx * TN + j];
            #pragma unroll
            for (int i = 0; i < TM; i++)
                #pragma unroll
                for (int j = 0; j < TN; j++)
                    acc[i][j] = fmaf(a[i], b[j], acc[i][j]);
        }
        __syncthreads();
    }
}

__device__ __forceinline__ void store_tile(float* __restrict__ C, long ldc,
                                           const float acc[TM][TN],
                                           const float bias[TN], float alpha) {
    const int tx = threadIdx.x & 15;
    const int ty = threadIdx.x >> 4;
    #pragma unroll
    for (int i = 0; i < TM; i++) {
        long roff = (long)(ty * TM + i) * ldc + tx * TN;
        float4 o0, o1;
        o0.x = acc[i][0] * alpha + bias[0];
        o0.y = acc[i][1] * alpha + bias[1];
        o0.z = acc[i][2] * alpha + bias[2];
        o0.w = acc[i][3] * alpha + bias[3];
        o1.x = acc[i][4] * alpha + bias[4];
        o1.y = acc[i][5] * alpha + bias[5];
        o1.z = acc[i][6] * alpha + bias[6];
        o1.w = acc[i][7] * alpha + bias[7];
        *reinterpret_cast<float4*>(&C[roff])     = o0;
        *reinterpret_cast<float4*>(&C[roff + 4]) = o1;
    }
}

// ------------------------------------------------------------------
// Stage 1: qkv[h][m][f] = sum_e x[m][e] * Wqkv[h][f][e] + bqkv[h][f]
// grid: (F3/BN=24, M1/BM=64, H=8)
// ------------------------------------------------------------------
__global__ __launch_bounds__(NTHR) void k_qkv(const float* __restrict__ x,
                                              const float* __restrict__ Wqkv,
                                              const float* __restrict__ bqkv) {
    __shared__ Smem s;
    const int h  = blockIdx.z;
    const int m0 = blockIdx.y * BM;
    const int n0 = blockIdx.x * BN;
    const float* A = x + (long)m0 * E_DIM;
    const float* B = Wqkv + (long)h * F3 * E_DIM + (long)n0 * E_DIM;
    float acc[TM][TN] = {};
    gemm_core<true>(A, E_DIM, B, E_DIM, E_DIM, s, acc);

    const int tx = threadIdx.x & 15;
    float bias[TN];
    #pragma unroll
    for (int j = 0; j < TN; j++) bias[j] = bqkv[(long)h * F3 + n0 + tx * TN + j];
    float* C = g_qkv + (long)h * M1 * F3 + (long)m0 * F3 + n0;
    store_tile(C, F3, acc, bias, 1.0f);
}

// ------------------------------------------------------------------
// Stage 2: scores[h][n][i][j] = scale * sum_e q[h,i,n,e] * k[h,j,n,e]
// grid: (L/BN=16, L/BM=16, H*N=32)
// ------------------------------------------------------------------
__global__ __launch_bounds__(NTHR) void k_scores() {
    __shared__ Smem s;
    const int z  = blockIdx.z;          // h*N + n
    const int h  = z / N_DIM;
    const int n  = z % N_DIM;
    const int i0 = blockIdx.y * BM;
    const int j0 = blockIdx.x * BN;
    const long base = (long)h * M1 * F3 + (long)n * F3;
    const float* A = g_qkv + base + (long)i0 * (N_DIM * F3);             // q rows
    const float* B = g_qkv + base + E_DIM + (long)j0 * (N_DIM * F3);     // k rows
    float acc[TM][TN] = {};
    gemm_core<true>(A, (long)N_DIM * F3, B, (long)N_DIM * F3, E_DIM, s, acc);

    float bias[TN] = {};
    float* C = g_scores + ((long)z * L_DIM + i0) * L_DIM + j0;
    store_tile(C, L_DIM, acc, bias, 0.03125f);   // 1/sqrt(1024)
}

// ------------------------------------------------------------------
// Softmax in place over last dim (rows = H*N*L = 65536, len 2048)
// ------------------------------------------------------------------
__global__ __launch_bounds__(NTHR) void k_softmax(float* __restrict__ S) {
    __shared__ float red_max[8];
    __shared__ float red_sum[8];
    const long row = blockIdx.x;
    float4* p = reinterpret_cast<float4*>(S + row * (long)L_DIM);
    const int t = threadIdx.x;
    float4 a = p[t];
    float4 b = p[t + 256];

    float m = fmaxf(fmaxf(fmaxf(a.x, a.y), fmaxf(a.z, a.w)),
                    fmaxf(fmaxf(b.x, b.y), fmaxf(b.z, b.w)));
    #pragma unroll
    for (int o = 16; o; o >>= 1) m = fmaxf(m, __shfl_xor_sync(0xFFFFFFFFu, m, o));
    if ((t & 31) == 0) red_max[t >> 5] = m;
    __syncthreads();
    float mall = red_max[0];
    #pragma unroll
    for (int i = 1; i < 8; i++) mall = fmaxf(mall, red_max[i]);

    a.x = __expf(a.x - mall); a.y = __expf(a.y - mall);
    a.z = __expf(a.z - mall); a.w = __expf(a.w - mall);
    b.x = __expf(b.x - mall); b.y = __expf(b.y - mall);
    b.z = __expf(b.z - mall); b.w = __expf(b.w - mall);

    float sum = a.x + a.y + a.z + a.w + b.x + b.y + b.z + b.w;
    #pragma unroll
    for (int o = 16; o; o >>= 1) sum += __shfl_xor_sync(0xFFFFFFFFu, sum, o);
    if ((t & 31) == 0) red_sum[t >> 5] = sum;
    __syncthreads();
    float stot = 0.f;
    #pragma unroll
    for (int i = 0; i < 8; i++) stot += red_sum[i];
    const float inv = 1.0f / stot;

    a.x *= inv; a.y *= inv; a.z *= inv; a.w *= inv;
    b.x *= inv; b.y *= inv; b.z *= inv; b.w *= inv;
    p[t] = a;
    p[t + 256] = b;
}

// ------------------------------------------------------------------
// Stage 3: ctx[h][(i*N+n)][e] = sum_j attn[h,n,i,j] * v[h,j,n,e]
// grid: (E/BN=8, L/BM=16, H*N=32)
// ------------------------------------------------------------------
__global__ __launch_bounds__(NTHR) void k_ctx() {
    __shared__ Smem s;
    const int z  = blockIdx.z;
    const int h  = z / N_DIM;
    const int n  = z % N_DIM;
    const int i0 = blockIdx.y * BM;
    const int e0 = blockIdx.x * BN;
    const float* A = g_scores + ((long)z * L_DIM + i0) * L_DIM;                 // attn[i,j]
    const float* B = g_qkv + (long)h * M1 * F3 + (long)n * F3 + 2 * E_DIM + e0; // v[j,e]
    float acc[TM][TN] = {};
    gemm_core<false>(A, L_DIM, B, (long)N_DIM * F3, L_DIM, s, acc);

    float bias[TN] = {};
    float* C = g_ctx + (long)h * M1 * E_DIM + ((long)i0 * N_DIM + n) * E_DIM + e0;
    store_tile(C, (long)N_DIM * E_DIM, acc, bias, 1.0f);
}

// ------------------------------------------------------------------
// Stage 4: out[m][f] = sum_h ( sum_e ctx[h][m][e] * Wo[h][f][e] + bo[h][f] )
// grid: (E/BN=8, M1/BM=64)
// ------------------------------------------------------------------
__global__ __launch_bounds__(NTHR) void k_out(const float* __restrict__ Wo,
                                              const float* __restrict__ bo,
                                              float* __restrict__ out) {
    __shared__ Smem s;
    const int m0 = blockIdx.y * BM;
    const int n0 = blockIdx.x * BN;
    float acc[TM][TN] = {};
    for (int h = 0; h < H_DIM; h++) {
        const float* A = g_ctx + (long)h * M1 * E_DIM + (long)m0 * E_DIM;
        const float* B = Wo + (long)h * E_DIM * E_DIM + (long)n0 * E_DIM;
        gemm_core<true>(A, E_DIM, B, E_DIM, E_DIM, s, acc);
    }
    const int tx = threadIdx.x & 15;
    float bias[TN];
    #pragma unroll
    for (int j = 0; j < TN; j++) {
        float bs = 0.f;
        #pragma unroll
        for (int h = 0; h < H_DIM; h++) bs += bo[(long)h * E_DIM + n0 + tx * TN + j];
        bias[j] = bs;
    }
    float* C = out + (long)m0 * E_DIM + n0;
    store_tile(C, E_DIM, acc, bias, 1.0f);
}

// ------------------------------------------------------------------
extern "C" void kernel_launch(void* const* d_in, const int* in_sizes, int n_in,
                              void* d_out, int out_size) {
    const float* x    = (const float*)d_in[0];
    const float* Wqkv = (const float*)d_in[1];
    const float* bqkv = (const float*)d_in[2];
    const float* Wo   = (const float*)d_in[3];
    const float* bo   = (const float*)d_in[4];
    float* out = (float*)d_out;

    float* scores_ptr = nullptr;
    cudaGetSymbolAddress((void**)&scores_ptr, g_scores);

    k_qkv<<<dim3(F3 / BN, M1 / BM, H_DIM), NTHR>>>(x, Wqkv, bqkv);
    k_scores<<<dim3(L_DIM / BN, L_DIM / BM, H_DIM * N_DIM), NTHR>>>();
    k_softmax<<<H_DIM * N_DIM * L_DIM, NTHR>>>(scores_ptr);
    k_ctx<<<dim3(E_DIM / BN, L_DIM / BM, H_DIM * N_DIM), NTHR>>>();
    k_out<<<dim3(E_DIM / BN, M1 / BM, 1), NTHR>>>(Wo, bo, out);
}

// round 3
// speedup vs baseline: 2.5621x; 2.5621x over previous
#include <cuda_runtime.h>
#include <cstdint>

#define L_DIM 2048
#define N_DIM 4
#define E_DIM 1024
#define H_DIM 8
#define M1    (L_DIM * N_DIM)   // 8192
#define F3    (3 * E_DIM)       // 3072

// ------------------------------------------------------------------
// Scratch (__device__ globals; allocation-free)
// ------------------------------------------------------------------
__device__ float g_qkv[(long long)H_DIM * M1 * F3];                    // [h][m][f]
__device__ float g_scores[(long long)H_DIM * N_DIM * L_DIM * L_DIM];  // [z][i][j]
__device__ float g_ctx[(long long)H_DIM * M1 * E_DIM];                 // [h][m][e]

// ------------------------------------------------------------------
// Tile config
// ------------------------------------------------------------------
#define BM 128
#define BN 128
#define BK 16
#define NSTAGE 3
#define NTHR 256
#define LDA_S 20      // A smem row stride (floats) -> conflict-free frag reads
#define LDB_NK 20     // B [n][k] smem row stride
#define LDB_KN 136    // B [k][n] smem row stride (136 mod 32 == 8 -> conflict-free)

#define A_SLOT_F (BM * LDA_S)       // 2560 floats per stage
#define B_SLOT_F (BM * LDB_NK)      // 2560 floats per stage (kn variant 16*136=2176 fits)
#define SMEM_DYN ((NSTAGE * A_SLOT_F + NSTAGE * B_SLOT_F) * 4)   // 61440 B

// ------------------------------------------------------------------
// PTX helpers (baseline compute_103-safe: no tcgen05)
// ------------------------------------------------------------------
__device__ __forceinline__ uint32_t smem_u32(const void* p) {
    uint32_t a;
    asm("{ .reg .u64 t; cvta.to.shared.u64 t, %1; cvt.u32.u64 %0, t; }" : "=r"(a) : "l"(p));
    return a;
}
__device__ __forceinline__ void cp_async16(uint32_t dst, const void* src) {
    asm volatile("cp.async.cg.shared.global [%0], [%1], 16;" :: "r"(dst), "l"(src));
}
__device__ __forceinline__ uint32_t f2tf32(float v) {
    uint32_t r;
    asm("cvt.rna.tf32.f32 %0, %1;" : "=r"(r) : "f"(v));
    return r;
}
__device__ __forceinline__ void mma_tf32(float c[4], const uint32_t a[4], const uint32_t b[2]) {
    asm volatile(
        "mma.sync.aligned.m16n8k8.row.col.f32.tf32.tf32.f32 "
        "{%0,%1,%2,%3}, {%4,%5,%6,%7}, {%8,%9}, {%0,%1,%2,%3};"
        : "+f"(c[0]), "+f"(c[1]), "+f"(c[2]), "+f"(c[3])
        : "r"(a[0]), "r"(a[1]), "r"(a[2]), "r"(a[3]), "r"(b[0]), "r"(b[1]));
}

// ------------------------------------------------------------------
// Templated GEMM. STAGE:
//  1: qkv = x @ Wqkv^T + bqkv          (A[m][k], B[n][k])
//  2: scores = scale * q @ k^T          (A,B strided rows of g_qkv)
//  3: ctx = attn @ V                    (B is [k][n]!)
//  4: out = sum_h ctx[h] @ Wo[h]^T + b  (K loop runs over h too)
// ------------------------------------------------------------------
template <int STAGE>
__global__ void __launch_bounds__(NTHR) gemm_mma(
    const float* __restrict__ Ain, const float* __restrict__ Bin,
    const float* __restrict__ bias, float* __restrict__ Cbase)
{
    constexpr bool BKN = (STAGE == 3);
    constexpr int NKT = (STAGE == 3) ? (L_DIM / BK) : (STAGE == 4 ? H_DIM * (E_DIM / BK) : (E_DIM / BK));
    constexpr float alpha = (STAGE == 2) ? 0.03125f : 1.0f;

    extern __shared__ float smem[];
    float* a_s = smem;
    float* b_s = smem + NSTAGE * A_SLOT_F;
    __shared__ float s_bias[BN];

    const int tid  = threadIdx.x;
    const int warp = tid >> 5;
    const int lane = tid & 31;
    const int wm   = warp >> 1;   // 0..3
    const int wn   = warp & 1;    // 0..1
    const int n0   = blockIdx.x * BN;
    const int m0   = blockIdx.y * BM;
    const int bz   = blockIdx.z;
    const int h    = bz >> 2;
    const int nn   = bz & 3;

    const uint32_t a_addr = smem_u32(a_s);
    const uint32_t b_addr = smem_u32(b_s);

    // bias into smem
    for (int i = tid; i < BN; i += NTHR) {
        if (STAGE == 1) {
            s_bias[i] = bias[(long long)bz * F3 + n0 + i];
        } else if (STAGE == 4) {
            float s = 0.f;
            #pragma unroll
            for (int hh = 0; hh < H_DIM; hh++) s += bias[(long long)hh * E_DIM + n0 + i];
            s_bias[i] = s;
        } else {
            s_bias[i] = 0.f;
        }
    }

    // Stage-specific global bases / strides
    const float* Ab;
    const float* Bb;
    long long ldA, ldB;
    if (STAGE == 1) {
        Ab = Ain;                         ldA = E_DIM;
        Bb = Bin + (long long)bz * F3 * E_DIM; ldB = E_DIM;
    } else if (STAGE == 2) {
        const float* q = Ain + (long long)h * M1 * F3 + (long long)nn * F3;
        Ab = q;          ldA = (long long)N_DIM * F3;
        Bb = q + E_DIM;  ldB = (long long)N_DIM * F3;
    } else if (STAGE == 3) {
        Ab = Ain + (long long)bz * L_DIM * L_DIM;                              ldA = L_DIM;
        Bb = Bin + (long long)h * M1 * F3 + (long long)nn * F3 + 2 * E_DIM;    ldB = (long long)N_DIM * F3;
    } else {
        Ab = Ain; ldA = E_DIM;
        Bb = Bin; ldB = E_DIM;
    }

    auto load_tile = [&](int kt, int slot) {
        const float* Abase = Ab;
        const float* Bbase = Bb;
        int kk;
        if (STAGE == 4) {
            const int hh = kt >> 6;
            kk = (kt & 63) * BK;
            Abase = Ab + (long long)hh * M1 * E_DIM;
            Bbase = Bb + (long long)hh * E_DIM * E_DIM;
        } else {
            kk = kt * BK;
        }
        // A: 128 rows x 16 floats -> 512 16B-chunks
        #pragma unroll
        for (int i = 0; i < 2; i++) {
            const int c = tid + i * NTHR;
            const int row = c >> 2;
            const int kc = (c & 3) << 2;
            const float* src = Abase + (long long)(m0 + row) * ldA + kk + kc;
            cp_async16(a_addr + (uint32_t)(slot * A_SLOT_F + row * LDA_S + kc) * 4u, src);
        }
        if (!BKN) {
            // B: [n][k] 128 rows x 16 floats
            #pragma unroll
            for (int i = 0; i < 2; i++) {
                const int c = tid + i * NTHR;
                const int row = c >> 2;
                const int kc = (c & 3) << 2;
                const float* src = Bbase + (long long)(n0 + row) * ldB + kk + kc;
                cp_async16(b_addr + (uint32_t)(slot * B_SLOT_F + row * LDB_NK + kc) * 4u, src);
            }
        } else {
            // B: [k][n] 16 rows x 128 floats
            #pragma unroll
            for (int i = 0; i < 2; i++) {
                const int c = tid + i * NTHR;
                const int krow = c >> 5;
                const int nc = (c & 31) << 2;
                const float* src = Bbase + (long long)(kk + krow) * ldB + n0 + nc;
                cp_async16(b_addr + (uint32_t)(slot * B_SLOT_F + krow * LDB_KN + nc) * 4u, src);
            }
        }
        asm volatile("cp.async.commit_group;" ::: "memory");
    };

    float acc[2][8][4] = {};

    load_tile(0, 0);
    load_tile(1, 1);
    asm volatile("cp.async.wait_group 1;" ::: "memory");
    __syncthreads();

    const int r  = lane >> 2;
    const int cl = lane & 3;

    for (int kt = 0; kt < NKT; kt++) {
        const int slot = kt % NSTAGE;
        if (kt + 2 < NKT) load_tile(kt + 2, (kt + 2) % NSTAGE);

        const float* As = a_s + slot * A_SLOT_F;
        const float* Bs = b_s + slot * B_SLOT_F;

        #pragma unroll
        for (int ks = 0; ks < 2; ks++) {
            uint32_t af[2][4];
            #pragma unroll
            for (int mi = 0; mi < 2; mi++) {
                const int rb = wm * 32 + mi * 16;
                af[mi][0] = f2tf32(As[(rb + r)     * LDA_S + ks * 8 + cl]);
                af[mi][1] = f2tf32(As[(rb + r + 8) * LDA_S + ks * 8 + cl]);
                af[mi][2] = f2tf32(As[(rb + r)     * LDA_S + ks * 8 + cl + 4]);
                af[mi][3] = f2tf32(As[(rb + r + 8) * LDA_S + ks * 8 + cl + 4]);
            }
            uint32_t bf[8][2];
            #pragma unroll
            for (int ni = 0; ni < 8; ni++) {
                const int cb = wn * 64 + ni * 8 + r;
                if (!BKN) {
                    bf[ni][0] = f2tf32(Bs[cb * LDB_NK + ks * 8 + cl]);
                    bf[ni][1] = f2tf32(Bs[cb * LDB_NK + ks * 8 + cl + 4]);
                } else {
                    bf[ni][0] = f2tf32(Bs[(ks * 8 + cl)     * LDB_KN + cb]);
                    bf[ni][1] = f2tf32(Bs[(ks * 8 + cl + 4) * LDB_KN + cb]);
                }
            }
            #pragma unroll
            for (int mi = 0; mi < 2; mi++)
                #pragma unroll
                for (int ni = 0; ni < 8; ni++)
                    mma_tf32(acc[mi][ni], af[mi], bf[ni]);
        }

        if (kt + 2 < NKT) {
            asm volatile("cp.async.wait_group 1;" ::: "memory");
        } else {
            asm volatile("cp.async.wait_group 0;" ::: "memory");
        }
        __syncthreads();
    }

    // ---------------- epilogue ----------------
    long long ldc;
    float* C;
    if (STAGE == 1) {
        ldc = F3;    C = Cbase + ((long long)bz * M1 + m0) * F3 + n0;
    } else if (STAGE == 2) {
        ldc = L_DIM; C = Cbase + ((long long)bz * L_DIM + m0) * L_DIM + n0;
    } else if (STAGE == 3) {
        ldc = (long long)N_DIM * E_DIM;
        C = Cbase + (long long)h * M1 * E_DIM + ((long long)m0 * N_DIM + nn) * E_DIM + n0;
    } else {
        ldc = E_DIM; C = Cbase + (long long)m0 * E_DIM + n0;
    }

    #pragma unroll
    for (int mi = 0; mi < 2; mi++) {
        #pragma unroll
        for (int ni = 0; ni < 8; ni++) {
            const int row = wm * 32 + mi * 16 + r;
            const int col = wn * 64 + ni * 8 + cl * 2;
            float2 v0, v1;
            v0.x = acc[mi][ni][0] * alpha + s_bias[col];
            v0.y = acc[mi][ni][1] * alpha + s_bias[col + 1];
            v1.x = acc[mi][ni][2] * alpha + s_bias[col];
            v1.y = acc[mi][ni][3] * alpha + s_bias[col + 1];
            *reinterpret_cast<float2*>(&C[(long long)row * ldc + col])       = v0;
            *reinterpret_cast<float2*>(&C[(long long)(row + 8) * ldc + col]) = v1;
        }
    }
}

// ------------------------------------------------------------------
// Softmax in place over last dim (rows = H*N*L = 65536, len 2048)
// ------------------------------------------------------------------
__global__ void __launch_bounds__(256) k_softmax(float* __restrict__ S) {
    __shared__ float red_max[8];
    __shared__ float red_sum[8];
    const long long row = blockIdx.x;
    float4* p = reinterpret_cast<float4*>(S + row * (long long)L_DIM);
    const int t = threadIdx.x;
    float4 a = p[t];
    float4 b = p[t + 256];

    float m = fmaxf(fmaxf(fmaxf(a.x, a.y), fmaxf(a.z, a.w)),
                    fmaxf(fmaxf(b.x, b.y), fmaxf(b.z, b.w)));
    #pragma unroll
    for (int o = 16; o; o >>= 1) m = fmaxf(m, __shfl_xor_sync(0xFFFFFFFFu, m, o));
    if ((t & 31) == 0) red_max[t >> 5] = m;
    __syncthreads();
    float mall = red_max[0];
    #pragma unroll
    for (int i = 1; i < 8; i++) mall = fmaxf(mall, red_max[i]);

    a.x = __expf(a.x - mall); a.y = __expf(a.y - mall);
    a.z = __expf(a.z - mall); a.w = __expf(a.w - mall);
    b.x = __expf(b.x - mall); b.y = __expf(b.y - mall);
    b.z = __expf(b.z - mall); b.w = __expf(b.w - mall);

    float sum = a.x + a.y + a.z + a.w + b.x + b.y + b.z + b.w;
    #pragma unroll
    for (int o = 16; o; o >>= 1) sum += __shfl_xor_sync(0xFFFFFFFFu, sum, o);
    if ((t & 31) == 0) red_sum[t >> 5] = sum;
    __syncthreads();
    float stot = 0.f;
    #pragma unroll
    for (int i = 0; i < 8; i++) stot += red_sum[i];
    const float inv = 1.0f / stot;

    a.x *= inv; a.y *= inv; a.z *= inv; a.w *= inv;
    b.x *= inv; b.y *= inv; b.z *= inv; b.w *= inv;
    p[t] = a;
    p[t + 256] = b;
}

// ------------------------------------------------------------------
// Host
// ------------------------------------------------------------------
extern "C" void kernel_launch(void* const* d_in, const int* in_sizes, int n_in,
                              void* d_out, int out_size) {
    const float* x    = (const float*)d_in[0];
    const float* Wqkv = (const float*)d_in[1];
    const float* bqkv = (const float*)d_in[2];
    const float* Wo   = (const float*)d_in[3];
    const float* bo   = (const float*)d_in[4];
    float* out = (float*)d_out;

    float *qkv, *scores, *ctx;
    cudaGetSymbolAddress((void**)&qkv, g_qkv);
    cudaGetSymbolAddress((void**)&scores, g_scores);
    cudaGetSymbolAddress((void**)&ctx, g_ctx);

    static bool attr_done = false;
    if (!attr_done) {
        cudaFuncSetAttribute(gemm_mma<1>, cudaFuncAttributeMaxDynamicSharedMemorySize, SMEM_DYN);
        cudaFuncSetAttribute(gemm_mma<2>, cudaFuncAttributeMaxDynamicSharedMemorySize, SMEM_DYN);
        cudaFuncSetAttribute(gemm_mma<3>, cudaFuncAttributeMaxDynamicSharedMemorySize, SMEM_DYN);
        cudaFuncSetAttribute(gemm_mma<4>, cudaFuncAttributeMaxDynamicSharedMemorySize, SMEM_DYN);
        attr_done = true;
    }

    // Stage 1: qkv = x @ Wqkv^T + bqkv
    gemm_mma<1><<<dim3(F3 / BN, M1 / BM, H_DIM), NTHR, SMEM_DYN>>>(x, Wqkv, bqkv, qkv);
    // Stage 2: scores = scale * q @ k^T
    gemm_mma<2><<<dim3(L_DIM / BN, L_DIM / BM, H_DIM * N_DIM), NTHR, SMEM_DYN>>>(qkv, qkv, nullptr, scores);
    // Softmax in place
    k_softmax<<<H_DIM * N_DIM * L_DIM, 256>>>(scores);
    // Stage 3: ctx = attn @ V   (B in [k][n] layout, read straight out of qkv)
    gemm_mma<3><<<dim3(E_DIM / BN, L_DIM / BM, H_DIM * N_DIM), NTHR, SMEM_DYN>>>(scores, qkv, nullptr, ctx);
    // Stage 4: out = sum_h ctx[h] @ Wo[h]^T + sum_h bo
    gemm_mma<4><<<dim3(E_DIM / BN, M1 / BM, 1), NTHR, SMEM_DYN>>>(ctx, Wo, bo, out);
}

// round 4
// speedup vs baseline: 6.0150x; 2.3477x over previous
#include <cuda_runtime.h>
#include <cuda_fp16.h>
#include <cstdint>

#define L_DIM 2048
#define N_DIM 4
#define E_DIM 1024
#define H_DIM 8
#define M1    (L_DIM * N_DIM)   // 8192
#define F3    (3 * E_DIM)       // 3072

// ------------------------------------------------------------------
// Scratch (__device__ globals; allocation-free)
// ------------------------------------------------------------------
__device__ __half g_xh  [(long long)M1 * E_DIM];                       // x fp16
__device__ __half g_wqkv[(long long)H_DIM * F3 * E_DIM];               // Wqkv fp16
__device__ __half g_wo  [(long long)H_DIM * E_DIM * E_DIM];            // Wo fp16
__device__ __half g_qkv [(long long)H_DIM * M1 * F3];                  // [h][m][f] fp16
__device__ float  g_scores[(long long)H_DIM * N_DIM * L_DIM * L_DIM]; // [z][i][j] fp32
__device__ __half g_attn[(long long)H_DIM * N_DIM * L_DIM * L_DIM];   // [z][i][j] fp16
__device__ __half g_ctx [(long long)H_DIM * M1 * E_DIM];               // [h][m][e] fp16

// ------------------------------------------------------------------
// Tile config (halves)
// ------------------------------------------------------------------
#define BM 128
#define BN 128
#define BK 32
#define NSTAGE 3
#define NTHR 256
#define LDA_S 40       // A smem row stride (halves): 80B -> ldmatrix conflict-free
#define LDB_NK 40      // B [n][k] row stride (halves)
#define LDB_KN 136     // B [k][n] row stride (halves): 272B -> conflict-free

#define A_SLOT_H (BM * LDA_S)     // 5120 halves
#define B_SLOT_H (BM * LDB_NK)    // 5120 halves (kn variant 32*136=4352 fits)
#define SMEM_DYN ((NSTAGE * A_SLOT_H + NSTAGE * B_SLOT_H) * 2)   // 61440 B

// ------------------------------------------------------------------
// PTX helpers (baseline compute_103-safe)
// ------------------------------------------------------------------
__device__ __forceinline__ uint32_t smem_u32(const void* p) {
    uint32_t a;
    asm("{ .reg .u64 t; cvta.to.shared.u64 t, %1; cvt.u32.u64 %0, t; }" : "=r"(a) : "l"(p));
    return a;
}
__device__ __forceinline__ void cp_async16(uint32_t dst, const void* src) {
    asm volatile("cp.async.cg.shared.global [%0], [%1], 16;" :: "r"(dst), "l"(src));
}
__device__ __forceinline__ void ldsm_x4(uint32_t& r0, uint32_t& r1, uint32_t& r2, uint32_t& r3,
                                        uint32_t addr) {
    asm volatile("ldmatrix.sync.aligned.m8n8.x4.shared.b16 {%0,%1,%2,%3}, [%4];"
                 : "=r"(r0), "=r"(r1), "=r"(r2), "=r"(r3) : "r"(addr));
}
__device__ __forceinline__ void ldsm_x4_t(uint32_t& r0, uint32_t& r1, uint32_t& r2, uint32_t& r3,
                                          uint32_t addr) {
    asm volatile("ldmatrix.sync.aligned.m8n8.x4.trans.shared.b16 {%0,%1,%2,%3}, [%4];"
                 : "=r"(r0), "=r"(r1), "=r"(r2), "=r"(r3) : "r"(addr));
}
__device__ __forceinline__ void mma_f16(float c[4], const uint32_t a[4], const uint32_t b[2]) {
    asm volatile(
        "mma.sync.aligned.m16n8k16.row.col.f32.f16.f16.f32 "
        "{%0,%1,%2,%3}, {%4,%5,%6,%7}, {%8,%9}, {%0,%1,%2,%3};"
        : "+f"(c[0]), "+f"(c[1]), "+f"(c[2]), "+f"(c[3])
        : "r"(a[0]), "r"(a[1]), "r"(a[2]), "r"(a[3]), "r"(b[0]), "r"(b[1]));
}

// ------------------------------------------------------------------
// Templated GEMM. STAGE:
//  1: qkv(h) = x @ Wqkv^T + bqkv       A[m][k] B[n][k]  -> C fp16
//  2: scores = scale * q @ k^T         strided fp16     -> C fp32
//  3: ctx(h) = attn @ V                B is [k][n]      -> C fp16
//  4: out = sum_h ctx[h]@Wo[h]^T + b   K loop over h    -> C fp32
// ------------------------------------------------------------------
template <int STAGE>
__global__ void __launch_bounds__(NTHR) gemm_mma(
    const __half* __restrict__ Ain, const __half* __restrict__ Bin,
    const float* __restrict__ bias, void* __restrict__ Cout)
{
    constexpr bool BKN = (STAGE == 3);
    constexpr bool CH  = (STAGE == 1 || STAGE == 3);   // fp16 output
    constexpr int  NKT = (STAGE == 3) ? (L_DIM / BK)
                        : (STAGE == 4 ? H_DIM * (E_DIM / BK) : (E_DIM / BK));
    constexpr float alpha = (STAGE == 2) ? 0.03125f : 1.0f;

    extern __shared__ __half smem[];
    __half* a_s = smem;
    __half* b_s = smem + NSTAGE * A_SLOT_H;
    __shared__ float s_bias[BN];

    const int tid  = threadIdx.x;
    const int warp = tid >> 5;
    const int lane = tid & 31;
    const int wm   = warp >> 1;   // 0..3
    const int wn   = warp & 1;    // 0..1
    const int n0   = blockIdx.x * BN;
    const int m0   = blockIdx.y * BM;
    const int bz   = blockIdx.z;
    const int h    = bz >> 2;
    const int nn   = bz & 3;

    const uint32_t a_addr = smem_u32(a_s);
    const uint32_t b_addr = smem_u32(b_s);

    for (int i = tid; i < BN; i += NTHR) {
        if (STAGE == 1) {
            s_bias[i] = bias[(long long)bz * F3 + n0 + i];
        } else if (STAGE == 4) {
            float s = 0.f;
            #pragma unroll
            for (int hh = 0; hh < H_DIM; hh++) s += bias[(long long)hh * E_DIM + n0 + i];
            s_bias[i] = s;
        } else {
            s_bias[i] = 0.f;
        }
    }

    const __half* Ab;
    const __half* Bb;
    long long ldA, ldB;
    if (STAGE == 1) {
        Ab = Ain;                                ldA = E_DIM;
        Bb = Bin + (long long)bz * F3 * E_DIM;   ldB = E_DIM;
    } else if (STAGE == 2) {
        const __half* q = Ain + (long long)h * M1 * F3 + (long long)nn * F3;
        Ab = q;          ldA = (long long)N_DIM * F3;
        Bb = q + E_DIM;  ldB = (long long)N_DIM * F3;
    } else if (STAGE == 3) {
        Ab = Ain + (long long)bz * L_DIM * L_DIM;                           ldA = L_DIM;
        Bb = Bin + (long long)h * M1 * F3 + (long long)nn * F3 + 2 * E_DIM; ldB = (long long)N_DIM * F3;
    } else {
        Ab = Ain; ldA = E_DIM;
        Bb = Bin; ldB = E_DIM;
    }

    auto load_tile = [&](int kt, int slot) {
        const __half* Abase = Ab;
        const __half* Bbase = Bb;
        int kk;
        if (STAGE == 4) {
            const int hh = kt >> 5;           // 32 k-tiles per head
            kk = (kt & 31) * BK;
            Abase = Ab + (long long)hh * M1 * E_DIM;
            Bbase = Bb + (long long)hh * E_DIM * E_DIM;
        } else {
            kk = kt * BK;
        }
        // A: 128 rows x 32 halves = 4 chunks/row -> 512 chunks
        #pragma unroll
        for (int i = 0; i < 2; i++) {
            const int c = tid + i * NTHR;
            const int row = c >> 2;
            const int kc = (c & 3) << 3;
            const __half* src = Abase + (long long)(m0 + row) * ldA + kk + kc;
            cp_async16(a_addr + (uint32_t)(slot * A_SLOT_H + row * LDA_S + kc) * 2u, src);
        }
        if (!BKN) {
            #pragma unroll
            for (int i = 0; i < 2; i++) {
                const int c = tid + i * NTHR;
                const int row = c >> 2;
                const int kc = (c & 3) << 3;
                const __half* src = Bbase + (long long)(n0 + row) * ldB + kk + kc;
                cp_async16(b_addr + (uint32_t)(slot * B_SLOT_H + row * LDB_NK + kc) * 2u, src);
            }
        } else {
            // B: [k][n] 32 rows x 128 halves = 16 chunks/row -> 512 chunks
            #pragma unroll
            for (int i = 0; i < 2; i++) {
                const int c = tid + i * NTHR;
                const int krow = c >> 4;
                const int nc = (c & 15) << 3;
                const __half* src = Bbase + (long long)(kk + krow) * ldB + n0 + nc;
                cp_async16(b_addr + (uint32_t)(slot * B_SLOT_H + krow * LDB_KN + nc) * 2u, src);
            }
        }
        asm volatile("cp.async.commit_group;" ::: "memory");
    };

    float acc[2][8][4] = {};

    load_tile(0, 0);
    load_tile(1, 1);
    asm volatile("cp.async.wait_group 1;" ::: "memory");
    __syncthreads();

    const int grp = lane >> 3;     // 0..3
    const int lr  = lane & 7;

    for (int kt = 0; kt < NKT; kt++) {
        const int slot = kt % NSTAGE;
        if (kt + 2 < NKT) load_tile(kt + 2, (kt + 2) % NSTAGE);

        const uint32_t As = a_addr + (uint32_t)(slot * A_SLOT_H) * 2u;
        const uint32_t Bs = b_addr + (uint32_t)(slot * B_SLOT_H) * 2u;

        #pragma unroll
        for (int ks = 0; ks < 2; ks++) {
            // A frags: 2 x ldmatrix.x4 (rows = lane%16, k half-col = (lane/16)*8)
            uint32_t af[2][4];
            {
                const int arow = (lane & 15);
                const int acol = ks * 16 + (lane >> 4) * 8;
                #pragma unroll
                for (int mi = 0; mi < 2; mi++) {
                    const uint32_t addr = As + (uint32_t)(((wm * 32 + mi * 16 + arow) * LDA_S + acol)) * 2u;
                    ldsm_x4(af[mi][0], af[mi][1], af[mi][2], af[mi][3], addr);
                }
            }
            // B frags: 4 x ldmatrix.x4, each covers two n8 tiles
            uint32_t bf[8][2];
            #pragma unroll
            for (int pair = 0; pair < 4; pair++) {
                uint32_t r0, r1, r2, r3;
                if (!BKN) {
                    const int nrow = wn * 64 + pair * 16 + ((grp >> 1) << 3) + lr;
                    const int koff = ks * 16 + ((grp & 1) << 3);
                    ldsm_x4(r0, r1, r2, r3, Bs + (uint32_t)(nrow * LDB_NK + koff) * 2u);
                } else {
                    const int krow = ks * 16 + ((grp & 1) << 3) + lr;
                    const int ncol = wn * 64 + pair * 16 + ((grp >> 1) << 3);
                    ldsm_x4_t(r0, r1, r2, r3, Bs + (uint32_t)(krow * LDB_KN + ncol) * 2u);
                }
                bf[pair * 2][0]     = r0;
                bf[pair * 2][1]     = r1;
                bf[pair * 2 + 1][0] = r2;
                bf[pair * 2 + 1][1] = r3;
            }
            #pragma unroll
            for (int mi = 0; mi < 2; mi++)
                #pragma unroll
                for (int ni = 0; ni < 8; ni++)
                    mma_f16(acc[mi][ni], af[mi], bf[ni]);
        }

        if (kt + 2 < NKT) {
            asm volatile("cp.async.wait_group 1;" ::: "memory");
        } else {
            asm volatile("cp.async.wait_group 0;" ::: "memory");
        }
        __syncthreads();
    }

    // ---------------- epilogue ----------------
    const int r  = lane >> 2;
    const int cl = lane & 3;

    long long ldc;
    long long coff;
    if (STAGE == 1) {
        ldc = F3;    coff = ((long long)bz * M1 + m0) * F3 + n0;
    } else if (STAGE == 2) {
        ldc = L_DIM; coff = ((long long)bz * L_DIM + m0) * L_DIM + n0;
    } else if (STAGE == 3) {
        ldc = (long long)N_DIM * E_DIM;
        coff = (long long)h * M1 * E_DIM + ((long long)m0 * N_DIM + nn) * E_DIM + n0;
    } else {
        ldc = E_DIM; coff = (long long)m0 * E_DIM + n0;
    }

    #pragma unroll
    for (int mi = 0; mi < 2; mi++) {
        #pragma unroll
        for (int ni = 0; ni < 8; ni++) {
            const int row = wm * 32 + mi * 16 + r;
            const int col = wn * 64 + ni * 8 + cl * 2;
            const float v00 = acc[mi][ni][0] * alpha + s_bias[col];
            const float v01 = acc[mi][ni][1] * alpha + s_bias[col + 1];
            const float v10 = acc[mi][ni][2] * alpha + s_bias[col];
            const float v11 = acc[mi][ni][3] * alpha + s_bias[col + 1];
            if (CH) {
                __half* C = (__half*)Cout + coff;
                *reinterpret_cast<__half2*>(&C[(long long)row * ldc + col]) =
                    __floats2half2_rn(v00, v01);
                *reinterpret_cast<__half2*>(&C[(long long)(row + 8) * ldc + col]) =
                    __floats2half2_rn(v10, v11);
            } else {
                float* C = (float*)Cout + coff;
                *reinterpret_cast<float2*>(&C[(long long)row * ldc + col])       = make_float2(v00, v01);
                *reinterpret_cast<float2*>(&C[(long long)(row + 8) * ldc + col]) = make_float2(v10, v11);
            }
        }
    }
}

// ------------------------------------------------------------------
// fp32 -> fp16 convert (vectorized, 4 elems/thread)
// ------------------------------------------------------------------
__global__ void __launch_bounds__(256) k_f2h(const float4* __restrict__ in,
                                             __half2* __restrict__ out, long long n4) {
    const long long i = (long long)blockIdx.x * blockDim.x + threadIdx.x;
    if (i < n4) {
        float4 v = in[i];
        out[2 * i]     = __floats2half2_rn(v.x, v.y);
        out[2 * i + 1] = __floats2half2_rn(v.z, v.w);
    }
}

// ------------------------------------------------------------------
// Softmax: read fp32 scores, write fp16 probs
// ------------------------------------------------------------------
__global__ void __launch_bounds__(256) k_softmax(const float* __restrict__ S,
                                                 __half* __restrict__ P) {
    __shared__ float red_max[8];
    __shared__ float red_sum[8];
    const long long row = blockIdx.x;
    const float4* p = reinterpret_cast<const float4*>(S + row * (long long)L_DIM);
    const int t = threadIdx.x;
    float4 a = p[t];
    float4 b = p[t + 256];

    float m = fmaxf(fmaxf(fmaxf(a.x, a.y), fmaxf(a.z, a.w)),
                    fmaxf(fmaxf(b.x, b.y), fmaxf(b.z, b.w)));
    #pragma unroll
    for (int o = 16; o; o >>= 1) m = fmaxf(m, __shfl_xor_sync(0xFFFFFFFFu, m, o));
    if ((t & 31) == 0) red_max[t >> 5] = m;
    __syncthreads();
    float mall = red_max[0];
    #pragma unroll
    for (int i = 1; i < 8; i++) mall = fmaxf(mall, red_max[i]);

    a.x = __expf(a.x - mall); a.y = __expf(a.y - mall);
    a.z = __expf(a.z - mall); a.w = __expf(a.w - mall);
    b.x = __expf(b.x - mall); b.y = __expf(b.y - mall);
    b.z = __expf(b.z - mall); b.w = __expf(b.w - mall);

    float sum = a.x + a.y + a.z + a.w + b.x + b.y + b.z + b.w;
    #pragma unroll
    for (int o = 16; o; o >>= 1) sum += __shfl_xor_sync(0xFFFFFFFFu, sum, o);
    if ((t & 31) == 0) red_sum[t >> 5] = sum;
    __syncthreads();
    float stot = 0.f;
    #pragma unroll
    for (int i = 0; i < 8; i++) stot += red_sum[i];
    const float inv = 1.0f / stot;

    __half2* q = reinterpret_cast<__half2*>(P + row * (long long)L_DIM);
    q[2 * t]           = __floats2half2_rn(a.x * inv, a.y * inv);
    q[2 * t + 1]       = __floats2half2_rn(a.z * inv, a.w * inv);
    q[512 + 2 * t]     = __floats2half2_rn(b.x * inv, b.y * inv);
    q[512 + 2 * t + 1] = __floats2half2_rn(b.z * inv, b.w * inv);
}

// ------------------------------------------------------------------
// Host
// ------------------------------------------------------------------
extern "C" void kernel_launch(void* const* d_in, const int* in_sizes, int n_in,
                              void* d_out, int out_size) {
    const float* x    = (const float*)d_in[0];
    const float* Wqkv = (const float*)d_in[1];
    const float* bqkv = (const float*)d_in[2];
    const float* Wo   = (const float*)d_in[3];
    const float* bo   = (const float*)d_in[4];
    float* out = (float*)d_out;

    __half *xh, *wqkvh, *woh, *qkv, *attn, *ctx;
    float* scores;
    cudaGetSymbolAddress((void**)&xh, g_xh);
    cudaGetSymbolAddress((void**)&wqkvh, g_wqkv);
    cudaGetSymbolAddress((void**)&woh, g_wo);
    cudaGetSymbolAddress((void**)&qkv, g_qkv);
    cudaGetSymbolAddress((void**)&scores, g_scores);
    cudaGetSymbolAddress((void**)&attn, g_attn);
    cudaGetSymbolAddress((void**)&ctx, g_ctx);

    static bool attr_done = false;
    if (!attr_done) {
        cudaFuncSetAttribute(gemm_mma<1>, cudaFuncAttributeMaxDynamicSharedMemorySize, SMEM_DYN);
        cudaFuncSetAttribute(gemm_mma<2>, cudaFuncAttributeMaxDynamicSharedMemorySize, SMEM_DYN);
        cudaFuncSetAttribute(gemm_mma<3>, cudaFuncAttributeMaxDynamicSharedMemorySize, SMEM_DYN);
        cudaFuncSetAttribute(gemm_mma<4>, cudaFuncAttributeMaxDynamicSharedMemorySize, SMEM_DYN);
        attr_done = true;
    }

    // Convert inputs to fp16
    {
        const long long nx = (long long)M1 * E_DIM / 4;
        const long long nw = (long long)H_DIM * F3 * E_DIM / 4;
        const long long no = (long long)H_DIM * E_DIM * E_DIM / 4;
        k_f2h<<<(unsigned)((nx + 255) / 256), 256>>>((const float4*)x, (__half2*)xh, nx);
        k_f2h<<<(unsigned)((nw + 255) / 256), 256>>>((const float4*)Wqkv, (__half2*)wqkvh, nw);
        k_f2h<<<(unsigned)((no + 255) / 256), 256>>>((const float4*)Wo, (__half2*)woh, no);
    }

    // Stage 1: qkv = x @ Wqkv^T + bqkv   (fp16 out)
    gemm_mma<1><<<dim3(F3 / BN, M1 / BM, H_DIM), NTHR, SMEM_DYN>>>(xh, wqkvh, bqkv, qkv);
    // Stage 2: scores = scale * q @ k^T  (fp32 out)
    gemm_mma<2><<<dim3(L_DIM / BN, L_DIM / BM, H_DIM * N_DIM), NTHR, SMEM_DYN>>>(qkv, qkv, nullptr, scores);
    // Softmax fp32 -> fp16 probs
    k_softmax<<<H_DIM * N_DIM * L_DIM, 256>>>(scores, attn);
    // Stage 3: ctx = attn @ V            (fp16 out; B [k][n] via ldmatrix.trans)
    gemm_mma<3><<<dim3(E_DIM / BN, L_DIM / BM, H_DIM * N_DIM), NTHR, SMEM_DYN>>>(attn, qkv, nullptr, ctx);
    // Stage 4: out = sum_h ctx[h] @ Wo[h]^T + sum_h bo  (fp32 out)
    gemm_mma<4><<<dim3(E_DIM / BN, M1 / BM, 1), NTHR, SMEM_DYN>>>(ctx, woh, bo, out);
}

// round 5
// speedup vs baseline: 8.3432x; 1.3871x over previous
#include <cuda_runtime.h>
#include <cuda_fp16.h>
#include <cstdint>

#define L_DIM 2048
#define N_DIM 4
#define E_DIM 1024
#define H_DIM 8
#define M1    (L_DIM * N_DIM)   // 8192
#define F3    (3 * E_DIM)       // 3072

// ------------------------------------------------------------------
// Scratch (__device__ globals; allocation-free)
// ------------------------------------------------------------------
__device__ __half g_xh  [(long long)M1 * E_DIM];
__device__ __half g_wqkv[(long long)H_DIM * F3 * E_DIM];
__device__ __half g_wo  [(long long)H_DIM * E_DIM * E_DIM];
__device__ __half g_qkv [(long long)H_DIM * M1 * F3];
__device__ float  g_scores[(long long)H_DIM * N_DIM * L_DIM * L_DIM];
__device__ __half g_attn[(long long)H_DIM * N_DIM * L_DIM * L_DIM];
__device__ __half g_ctx [(long long)H_DIM * M1 * E_DIM];

// ------------------------------------------------------------------
// Tile config: BM=BN=128, BK=64 (4 x k16 steps), 3-stage cp.async
// SMEM per stage: A 16KB + B 16KB (XOR-swizzled, no padding)
// ------------------------------------------------------------------
#define BM 128
#define BN 128
#define BK 64
#define NSTAGE 3
#define NTHR 256

#define A_SLOT_B 16384      // 128 rows * 128 B
#define B_SLOT_B 16384      // nk: 128*128B ; kn: 64*256B
#define STAGE_B  (A_SLOT_B + B_SLOT_B)
#define SMEM_DYN (NSTAGE * STAGE_B)   // 98304 B

// ------------------------------------------------------------------
// PTX helpers
// ------------------------------------------------------------------
__device__ __forceinline__ uint32_t smem_u32(const void* p) {
    uint32_t a;
    asm("{ .reg .u64 t; cvta.to.shared.u64 t, %1; cvt.u32.u64 %0, t; }" : "=r"(a) : "l"(p));
    return a;
}
__device__ __forceinline__ void cp_async16(uint32_t dst, const void* src) {
    asm volatile("cp.async.cg.shared.global [%0], [%1], 16;" :: "r"(dst), "l"(src));
}
__device__ __forceinline__ void ldsm_x4(uint32_t& r0, uint32_t& r1, uint32_t& r2, uint32_t& r3,
                                        uint32_t addr) {
    asm volatile("ldmatrix.sync.aligned.m8n8.x4.shared.b16 {%0,%1,%2,%3}, [%4];"
                 : "=r"(r0), "=r"(r1), "=r"(r2), "=r"(r3) : "r"(addr));
}
__device__ __forceinline__ void ldsm_x4_t(uint32_t& r0, uint32_t& r1, uint32_t& r2, uint32_t& r3,
                                          uint32_t addr) {
    asm volatile("ldmatrix.sync.aligned.m8n8.x4.trans.shared.b16 {%0,%1,%2,%3}, [%4];"
                 : "=r"(r0), "=r"(r1), "=r"(r2), "=r"(r3) : "r"(addr));
}
__device__ __forceinline__ void mma_f16(float c[4], const uint32_t a[4], const uint32_t b[2]) {
    asm volatile(
        "mma.sync.aligned.m16n8k16.row.col.f32.f16.f16.f32 "
        "{%0,%1,%2,%3}, {%4,%5,%6,%7}, {%8,%9}, {%0,%1,%2,%3};"
        : "+f"(c[0]), "+f"(c[1]), "+f"(c[2]), "+f"(c[3])
        : "r"(a[0]), "r"(a[1]), "r"(a[2]), "r"(a[3]), "r"(b[0]), "r"(b[1]));
}

// Swizzled byte offsets (rows of 128B: 8 x 16B chunks, chunk ^= row&7)
__device__ __forceinline__ uint32_t sw_ab(int row, int kc /*half idx*/) {
    return (uint32_t)(row * 128 + ((((kc >> 3) & 7) ^ (row & 7)) << 4));
}
// kn layout: 64 rows x 256B (two 128B sub-blocks per row)
__device__ __forceinline__ uint32_t sw_kn(int krow, int nc /*half idx*/) {
    return (uint32_t)(krow * 256 + ((nc >> 6) << 7) + ((((nc >> 3) & 7) ^ (krow & 7)) << 4));
}

// ------------------------------------------------------------------
// Templated GEMM. STAGE:
//  1: qkv(h) = x @ Wqkv^T + bqkv       A[m][k] B[n][k]  -> C fp16
//  2: scores = scale * q @ k^T         strided fp16     -> C fp32
//  3: ctx(h) = attn @ V                B is [k][n]      -> C fp16
//  4: out = sum_h ctx[h]@Wo[h]^T + b   K loop over h    -> C fp32
// ------------------------------------------------------------------
template <int STAGE>
__global__ void __launch_bounds__(NTHR, 2) gemm_mma(
    const __half* __restrict__ Ain, const __half* __restrict__ Bin,
    const float* __restrict__ bias, void* __restrict__ Cout)
{
    constexpr bool BKN = (STAGE == 3);
    constexpr bool CH  = (STAGE == 1 || STAGE == 3);
    constexpr int  NKT = (STAGE == 3) ? (L_DIM / BK)
                        : (STAGE == 4 ? H_DIM * (E_DIM / BK) : (E_DIM / BK));
    constexpr float alpha = (STAGE == 2) ? 0.03125f : 1.0f;

    extern __shared__ __align__(1024) char smem[];
    __shared__ float s_bias[BN];

    const int tid  = threadIdx.x;
    const int warp = tid >> 5;
    const int lane = tid & 31;
    const int wm   = warp >> 1;
    const int wn   = warp & 1;
    const int n0   = blockIdx.x * BN;
    const int m0   = blockIdx.y * BM;
    const int bz   = blockIdx.z;
    const int h    = bz >> 2;
    const int nn   = bz & 3;

    const uint32_t s_base = smem_u32(smem);

    for (int i = tid; i < BN; i += NTHR) {
        if (STAGE == 1) {
            s_bias[i] = bias[(long long)bz * F3 + n0 + i];
        } else if (STAGE == 4) {
            float s = 0.f;
            #pragma unroll
            for (int hh = 0; hh < H_DIM; hh++) s += bias[(long long)hh * E_DIM + n0 + i];
            s_bias[i] = s;
        } else {
            s_bias[i] = 0.f;
        }
    }

    const __half* Ab;
    const __half* Bb;
    long long ldA, ldB;
    if (STAGE == 1) {
        Ab = Ain;                                ldA = E_DIM;
        Bb = Bin + (long long)bz * F3 * E_DIM;   ldB = E_DIM;
    } else if (STAGE == 2) {
        const __half* q = Ain + (long long)h * M1 * F3 + (long long)nn * F3;
        Ab = q;          ldA = (long long)N_DIM * F3;
        Bb = q + E_DIM;  ldB = (long long)N_DIM * F3;
    } else if (STAGE == 3) {
        Ab = Ain + (long long)bz * L_DIM * L_DIM;                           ldA = L_DIM;
        Bb = Bin + (long long)h * M1 * F3 + (long long)nn * F3 + 2 * E_DIM; ldB = (long long)N_DIM * F3;
    } else {
        Ab = Ain; ldA = E_DIM;
        Bb = Bin; ldB = E_DIM;
    }

    auto load_tile = [&](int kt, int slot) {
        const __half* Abase = Ab;
        const __half* Bbase = Bb;
        int kk;
        if (STAGE == 4) {
            const int hh = kt >> 4;           // 16 k-tiles per head
            kk = (kt & 15) * BK;
            Abase = Ab + (long long)hh * M1 * E_DIM;
            Bbase = Bb + (long long)hh * E_DIM * E_DIM;
        } else {
            kk = kt * BK;
        }
        const uint32_t a_sl = s_base + slot * STAGE_B;
        const uint32_t b_sl = a_sl + A_SLOT_B;
        // A: 128 rows x 64 halves -> 1024 16B-chunks
        #pragma unroll
        for (int i = 0; i < 4; i++) {
            const int c = tid + i * NTHR;
            const int row = c >> 3;
            const int kc = (c & 7) << 3;
            const __half* src = Abase + (long long)(m0 + row) * ldA + kk + kc;
            cp_async16(a_sl + sw_ab(row, kc), src);
        }
        if (!BKN) {
            #pragma unroll
            for (int i = 0; i < 4; i++) {
                const int c = tid + i * NTHR;
                const int row = c >> 3;
                const int kc = (c & 7) << 3;
                const __half* src = Bbase + (long long)(n0 + row) * ldB + kk + kc;
                cp_async16(b_sl + sw_ab(row, kc), src);
            }
        } else {
            // B: [k][n] 64 rows x 128 halves -> 1024 chunks
            #pragma unroll
            for (int i = 0; i < 4; i++) {
                const int c = tid + i * NTHR;
                const int krow = c >> 4;
                const int nc = (c & 15) << 3;
                const __half* src = Bbase + (long long)(kk + krow) * ldB + n0 + nc;
                cp_async16(b_sl + sw_kn(krow, nc), src);
            }
        }
        asm volatile("cp.async.commit_group;" ::: "memory");
    };

    float acc[2][8][4] = {};

    load_tile(0, 0);
    load_tile(1, 1);
    asm volatile("cp.async.wait_group 1;" ::: "memory");
    __syncthreads();

    const int grp = lane >> 3;
    const int lr  = lane & 7;
    const int arow = lane & 15;
    const int asel = lane >> 4;

    for (int kt = 0; kt < NKT; kt++) {
        const int slot = kt % NSTAGE;
        if (kt + 2 < NKT) load_tile(kt + 2, (kt + 2) % NSTAGE);

        const uint32_t As = s_base + slot * STAGE_B;
        const uint32_t Bs = As + A_SLOT_B;

        #pragma unroll
        for (int ks = 0; ks < 4; ks++) {
            uint32_t af[2][4];
            #pragma unroll
            for (int mi = 0; mi < 2; mi++) {
                const int row = wm * 32 + mi * 16 + arow;
                const int kc = ks * 16 + asel * 8;
                ldsm_x4(af[mi][0], af[mi][1], af[mi][2], af[mi][3], As + sw_ab(row, kc));
            }
            uint32_t bf[8][2];
            #pragma unroll
            for (int pair = 0; pair < 4; pair++) {
                uint32_t r0, r1, r2, r3;
                if (!BKN) {
                    const int nrow = wn * 64 + pair * 16 + ((grp >> 1) << 3) + lr;
                    const int kc = ks * 16 + ((grp & 1) << 3);
                    ldsm_x4(r0, r1, r2, r3, Bs + sw_ab(nrow, kc));
                } else {
                    const int krow = ks * 16 + ((grp & 1) << 3) + lr;
                    const int ncol = wn * 64 + pair * 16 + ((grp >> 1) << 3);
                    ldsm_x4_t(r0, r1, r2, r3, Bs + sw_kn(krow, ncol));
                }
                bf[pair * 2][0]     = r0;
                bf[pair * 2][1]     = r1;
                bf[pair * 2 + 1][0] = r2;
                bf[pair * 2 + 1][1] = r3;
            }
            #pragma unroll
            for (int mi = 0; mi < 2; mi++)
                #pragma unroll
                for (int ni = 0; ni < 8; ni++)
                    mma_f16(acc[mi][ni], af[mi], bf[ni]);
        }

        if (kt + 2 < NKT) {
            asm volatile("cp.async.wait_group 1;" ::: "memory");
        } else {
            asm volatile("cp.async.wait_group 0;" ::: "memory");
        }
        __syncthreads();
    }

    // ---------------- epilogue ----------------
    const int r  = lane >> 2;
    const int cl = lane & 3;

    long long ldc, coff;
    if (STAGE == 1) {
        ldc = F3;    coff = ((long long)bz * M1 + m0) * F3 + n0;
    } else if (STAGE == 2) {
        ldc = L_DIM; coff = ((long long)bz * L_DIM + m0) * L_DIM + n0;
    } else if (STAGE == 3) {
        ldc = (long long)N_DIM * E_DIM;
        coff = (long long)h * M1 * E_DIM + ((long long)m0 * N_DIM + nn) * E_DIM + n0;
    } else {
        ldc = E_DIM; coff = (long long)m0 * E_DIM + n0;
    }

    #pragma unroll
    for (int mi = 0; mi < 2; mi++) {
        #pragma unroll
        for (int ni = 0; ni < 8; ni++) {
            const int row = wm * 32 + mi * 16 + r;
            const int col = wn * 64 + ni * 8 + cl * 2;
            const float v00 = acc[mi][ni][0] * alpha + s_bias[col];
            const float v01 = acc[mi][ni][1] * alpha + s_bias[col + 1];
            const float v10 = acc[mi][ni][2] * alpha + s_bias[col];
            const float v11 = acc[mi][ni][3] * alpha + s_bias[col + 1];
            if (CH) {
                __half* C = (__half*)Cout + coff;
                *reinterpret_cast<__half2*>(&C[(long long)row * ldc + col]) =
                    __floats2half2_rn(v00, v01);
                *reinterpret_cast<__half2*>(&C[(long long)(row + 8) * ldc + col]) =
                    __floats2half2_rn(v10, v11);
            } else {
                float* C = (float*)Cout + coff;
                *reinterpret_cast<float2*>(&C[(long long)row * ldc + col])       = make_float2(v00, v01);
                *reinterpret_cast<float2*>(&C[(long long)(row + 8) * ldc + col]) = make_float2(v10, v11);
            }
        }
    }
}

// ------------------------------------------------------------------
// fp32 -> fp16 convert
// ------------------------------------------------------------------
__global__ void __launch_bounds__(256) k_f2h(const float4* __restrict__ in,
                                             __half2* __restrict__ out, long long n4) {
    const long long i = (long long)blockIdx.x * blockDim.x + threadIdx.x;
    if (i < n4) {
        float4 v = in[i];
        out[2 * i]     = __floats2half2_rn(v.x, v.y);
        out[2 * i + 1] = __floats2half2_rn(v.z, v.w);
    }
}

// ------------------------------------------------------------------
// Softmax: fp32 scores -> fp16 probs
// ------------------------------------------------------------------
__global__ void __launch_bounds__(256) k_softmax(const float* __restrict__ S,
                                                 __half* __restrict__ P) {
    __shared__ float red_max[8];
    __shared__ float red_sum[8];
    const long long row = blockIdx.x;
    const float4* p = reinterpret_cast<const float4*>(S + row * (long long)L_DIM);
    const int t = threadIdx.x;
    float4 a = p[t];
    float4 b = p[t + 256];

    float m = fmaxf(fmaxf(fmaxf(a.x, a.y), fmaxf(a.z, a.w)),
                    fmaxf(fmaxf(b.x, b.y), fmaxf(b.z, b.w)));
    #pragma unroll
    for (int o = 16; o; o >>= 1) m = fmaxf(m, __shfl_xor_sync(0xFFFFFFFFu, m, o));
    if ((t & 31) == 0) red_max[t >> 5] = m;
    __syncthreads();
    float mall = red_max[0];
    #pragma unroll
    for (int i = 1; i < 8; i++) mall = fmaxf(mall, red_max[i]);

    a.x = __expf(a.x - mall); a.y = __expf(a.y - mall);
    a.z = __expf(a.z - mall); a.w = __expf(a.w - mall);
    b.x = __expf(b.x - mall); b.y = __expf(b.y - mall);
    b.z = __expf(b.z - mall); b.w = __expf(b.w - mall);

    float sum = a.x + a.y + a.z + a.w + b.x + b.y + b.z + b.w;
    #pragma unroll
    for (int o = 16; o; o >>= 1) sum += __shfl_xor_sync(0xFFFFFFFFu, sum, o);
    if ((t & 31) == 0) red_sum[t >> 5] = sum;
    __syncthreads();
    float stot = 0.f;
    #pragma unroll
    for (int i = 0; i < 8; i++) stot += red_sum[i];
    const float inv = 1.0f / stot;

    __half2* q = reinterpret_cast<__half2*>(P + row * (long long)L_DIM);
    q[2 * t]           = __floats2half2_rn(a.x * inv, a.y * inv);
    q[2 * t + 1]       = __floats2half2_rn(a.z * inv, a.w * inv);
    q[512 + 2 * t]     = __floats2half2_rn(b.x * inv, b.y * inv);
    q[512 + 2 * t + 1] = __floats2half2_rn(b.z * inv, b.w * inv);
}

// ------------------------------------------------------------------
// Host
// ------------------------------------------------------------------
extern "C" void kernel_launch(void* const* d_in, const int* in_sizes, int n_in,
                              void* d_out, int out_size) {
    const float* x    = (const float*)d_in[0];
    const float* Wqkv = (const float*)d_in[1];
    const float* bqkv = (const float*)d_in[2];
    const float* Wo   = (const float*)d_in[3];
    const float* bo   = (const float*)d_in[4];
    float* out = (float*)d_out;

    __half *xh, *wqkvh, *woh, *qkv, *attn, *ctx;
    float* scores;
    cudaGetSymbolAddress((void**)&xh, g_xh);
    cudaGetSymbolAddress((void**)&wqkvh, g_wqkv);
    cudaGetSymbolAddress((void**)&woh, g_wo);
    cudaGetSymbolAddress((void**)&qkv, g_qkv);
    cudaGetSymbolAddress((void**)&scores, g_scores);
    cudaGetSymbolAddress((void**)&attn, g_attn);
    cudaGetSymbolAddress((void**)&ctx, g_ctx);

    static bool attr_done = false;
    if (!attr_done) {
        cudaFuncSetAttribute(gemm_mma<1>, cudaFuncAttributeMaxDynamicSharedMemorySize, SMEM_DYN);
        cudaFuncSetAttribute(gemm_mma<2>, cudaFuncAttributeMaxDynamicSharedMemorySize, SMEM_DYN);
        cudaFuncSetAttribute(gemm_mma<3>, cudaFuncAttributeMaxDynamicSharedMemorySize, SMEM_DYN);
        cudaFuncSetAttribute(gemm_mma<4>, cudaFuncAttributeMaxDynamicSharedMemorySize, SMEM_DYN);
        attr_done = true;
    }

    {
        const long long nx = (long long)M1 * E_DIM / 4;
        const long long nw = (long long)H_DIM * F3 * E_DIM / 4;
        const long long no = (long long)H_DIM * E_DIM * E_DIM / 4;
        k_f2h<<<(unsigned)((nx + 255) / 256), 256>>>((const float4*)x, (__half2*)xh, nx);
        k_f2h<<<(unsigned)((nw + 255) / 256), 256>>>((const float4*)Wqkv, (__half2*)wqkvh, nw);
        k_f2h<<<(unsigned)((no + 255) / 256), 256>>>((const float4*)Wo, (__half2*)woh, no);
    }

    gemm_mma<1><<<dim3(F3 / BN, M1 / BM, H_DIM), NTHR, SMEM_DYN>>>(xh, wqkvh, bqkv, qkv);
    gemm_mma<2><<<dim3(L_DIM / BN, L_DIM / BM, H_DIM * N_DIM), NTHR, SMEM_DYN>>>(qkv, qkv, nullptr, scores);
    k_softmax<<<H_DIM * N_DIM * L_DIM, 256>>>(scores, attn);
    gemm_mma<3><<<dim3(E_DIM / BN, L_DIM / BM, H_DIM * N_DIM), NTHR, SMEM_DYN>>>(attn, qkv, nullptr, ctx);
    gemm_mma<4><<<dim3(E_DIM / BN, M1 / BM, 1), NTHR, SMEM_DYN>>>(ctx, woh, bo, out);
}

// round 6
// speedup vs baseline: 8.4501x; 1.0128x over previous
#include <cuda_runtime.h>
#include <cuda_fp16.h>
#include <cstdint>

#define L_DIM 2048
#define N_DIM 4
#define E_DIM 1024
#define H_DIM 8
#define M1    (L_DIM * N_DIM)   // 8192
#define F3    (3 * E_DIM)       // 3072

// ------------------------------------------------------------------
// Scratch (__device__ globals; allocation-free)
// ------------------------------------------------------------------
__device__ __half g_xh  [(long long)M1 * E_DIM];
__device__ __half g_wqkv[(long long)H_DIM * F3 * E_DIM];
__device__ __half g_wo  [(long long)H_DIM * E_DIM * E_DIM];
__device__ __half g_qkv [(long long)H_DIM * M1 * F3];
__device__ float  g_scores[(long long)H_DIM * N_DIM * L_DIM * L_DIM];
__device__ __half g_attn[(long long)H_DIM * N_DIM * L_DIM * L_DIM];
__device__ __half g_ctx [(long long)H_DIM * M1 * E_DIM];

// ------------------------------------------------------------------
// Tile config: block 128x128, BK=64, 3-stage cp.async,
// 4 warps (128 thr), warp tile 64x64.
// ------------------------------------------------------------------
#define BM 128
#define BN 128
#define BK 64
#define NSTAGE 3
#define NTHR 128

#define A_SLOT_B 16384      // 128 rows * 128 B
#define B_SLOT_B 16384
#define STAGE_B  (A_SLOT_B + B_SLOT_B)
#define SMEM_DYN (NSTAGE * STAGE_B)   // 98304 B

// ------------------------------------------------------------------
// PTX helpers
// ------------------------------------------------------------------
__device__ __forceinline__ uint32_t smem_u32(const void* p) {
    uint32_t a;
    asm("{ .reg .u64 t; cvta.to.shared.u64 t, %1; cvt.u32.u64 %0, t; }" : "=r"(a) : "l"(p));
    return a;
}
__device__ __forceinline__ void cp_async16(uint32_t dst, const void* src) {
    asm volatile("cp.async.cg.shared.global [%0], [%1], 16;" :: "r"(dst), "l"(src));
}
__device__ __forceinline__ void ldsm_x4(uint32_t& r0, uint32_t& r1, uint32_t& r2, uint32_t& r3,
                                        uint32_t addr) {
    asm volatile("ldmatrix.sync.aligned.m8n8.x4.shared.b16 {%0,%1,%2,%3}, [%4];"
                 : "=r"(r0), "=r"(r1), "=r"(r2), "=r"(r3) : "r"(addr));
}
__device__ __forceinline__ void ldsm_x4_t(uint32_t& r0, uint32_t& r1, uint32_t& r2, uint32_t& r3,
                                          uint32_t addr) {
    asm volatile("ldmatrix.sync.aligned.m8n8.x4.trans.shared.b16 {%0,%1,%2,%3}, [%4];"
                 : "=r"(r0), "=r"(r1), "=r"(r2), "=r"(r3) : "r"(addr));
}
__device__ __forceinline__ void mma_f16(float c[4], const uint32_t a[4], const uint32_t b[2]) {
    asm volatile(
        "mma.sync.aligned.m16n8k16.row.col.f32.f16.f16.f32 "
        "{%0,%1,%2,%3}, {%4,%5,%6,%7}, {%8,%9}, {%0,%1,%2,%3};"
        : "+f"(c[0]), "+f"(c[1]), "+f"(c[2]), "+f"(c[3])
        : "r"(a[0]), "r"(a[1]), "r"(a[2]), "r"(a[3]), "r"(b[0]), "r"(b[1]));
}

// Swizzled byte offsets (rows of 128B: 8 x 16B chunks, chunk ^= row&7)
__device__ __forceinline__ uint32_t sw_ab(int row, int kc /*half idx*/) {
    return (uint32_t)(row * 128 + ((((kc >> 3) & 7) ^ (row & 7)) << 4));
}
// kn layout: 64 rows x 256B (two 128B sub-blocks per row)
__device__ __forceinline__ uint32_t sw_kn(int krow, int nc /*half idx*/) {
    return (uint32_t)(krow * 256 + ((nc >> 6) << 7) + ((((nc >> 3) & 7) ^ (krow & 7)) << 4));
}

// ------------------------------------------------------------------
// Templated GEMM. STAGE:
//  1: qkv(h) = x @ Wqkv^T + bqkv       A[m][k] B[n][k]  -> C fp16
//  2: scores = scale * q @ k^T         strided fp16     -> C fp32
//  3: ctx(h) = attn @ V                B is [k][n]      -> C fp16
//  4: out = sum_h ctx[h]@Wo[h]^T + b   K loop over h    -> C fp32
// ------------------------------------------------------------------
template <int STAGE>
__global__ void __launch_bounds__(NTHR, 2) gemm_mma(
    const __half* __restrict__ Ain, const __half* __restrict__ Bin,
    const float* __restrict__ bias, void* __restrict__ Cout)
{
    constexpr bool BKN = (STAGE == 3);
    constexpr bool CH  = (STAGE == 1 || STAGE == 3);
    constexpr int  NKT = (STAGE == 3) ? (L_DIM / BK)
                        : (STAGE == 4 ? H_DIM * (E_DIM / BK) : (E_DIM / BK));
    constexpr float alpha = (STAGE == 2) ? 0.03125f : 1.0f;

    extern __shared__ __align__(1024) char smem[];
    __shared__ float s_bias[BN];

    const int tid  = threadIdx.x;
    const int warp = tid >> 5;
    const int lane = tid & 31;
    const int wm   = warp >> 1;   // 0..1 (64-row halves)
    const int wn   = warp & 1;    // 0..1 (64-col halves)
    const int n0   = blockIdx.x * BN;
    const int m0   = blockIdx.y * BM;
    const int bz   = blockIdx.z;
    const int h    = bz >> 2;
    const int nn   = bz & 3;

    const uint32_t s_base = smem_u32(smem);

    for (int i = tid; i < BN; i += NTHR) {
        if (STAGE == 1) {
            s_bias[i] = bias[(long long)bz * F3 + n0 + i];
        } else if (STAGE == 4) {
            float s = 0.f;
            #pragma unroll
            for (int hh = 0; hh < H_DIM; hh++) s += bias[(long long)hh * E_DIM + n0 + i];
            s_bias[i] = s;
        } else {
            s_bias[i] = 0.f;
        }
    }

    const __half* Ab;
    const __half* Bb;
    long long ldA, ldB;
    if (STAGE == 1) {
        Ab = Ain;                                ldA = E_DIM;
        Bb = Bin + (long long)bz * F3 * E_DIM;   ldB = E_DIM;
    } else if (STAGE == 2) {
        const __half* q = Ain + (long long)h * M1 * F3 + (long long)nn * F3;
        Ab = q;          ldA = (long long)N_DIM * F3;
        Bb = q + E_DIM;  ldB = (long long)N_DIM * F3;
    } else if (STAGE == 3) {
        Ab = Ain + (long long)bz * L_DIM * L_DIM;                           ldA = L_DIM;
        Bb = Bin + (long long)h * M1 * F3 + (long long)nn * F3 + 2 * E_DIM; ldB = (long long)N_DIM * F3;
    } else {
        Ab = Ain; ldA = E_DIM;
        Bb = Bin; ldB = E_DIM;
    }

    auto load_tile = [&](int kt, int slot) {
        const __half* Abase = Ab;
        const __half* Bbase = Bb;
        int kk;
        if (STAGE == 4) {
            const int hh = kt >> 4;           // 16 k-tiles per head
            kk = (kt & 15) * BK;
            Abase = Ab + (long long)hh * M1 * E_DIM;
            Bbase = Bb + (long long)hh * E_DIM * E_DIM;
        } else {
            kk = kt * BK;
        }
        const uint32_t a_sl = s_base + slot * STAGE_B;
        const uint32_t b_sl = a_sl + A_SLOT_B;
        // A: 128 rows x 64 halves -> 1024 16B-chunks (8 per thread)
        #pragma unroll
        for (int i = 0; i < 8; i++) {
            const int c = tid + i * NTHR;
            const int row = c >> 3;
            const int kc = (c & 7) << 3;
            const __half* src = Abase + (long long)(m0 + row) * ldA + kk + kc;
            cp_async16(a_sl + sw_ab(row, kc), src);
        }
        if (!BKN) {
            #pragma unroll
            for (int i = 0; i < 8; i++) {
                const int c = tid + i * NTHR;
                const int row = c >> 3;
                const int kc = (c & 7) << 3;
                const __half* src = Bbase + (long long)(n0 + row) * ldB + kk + kc;
                cp_async16(b_sl + sw_ab(row, kc), src);
            }
        } else {
            // B: [k][n] 64 rows x 128 halves -> 1024 chunks
            #pragma unroll
            for (int i = 0; i < 8; i++) {
                const int c = tid + i * NTHR;
                const int krow = c >> 4;
                const int nc = (c & 15) << 3;
                const __half* src = Bbase + (long long)(kk + krow) * ldB + n0 + nc;
                cp_async16(b_sl + sw_kn(krow, nc), src);
            }
        }
        asm volatile("cp.async.commit_group;" ::: "memory");
    };

    float acc[4][8][4] = {};

    load_tile(0, 0);
    load_tile(1, 1);
    asm volatile("cp.async.wait_group 1;" ::: "memory");
    __syncthreads();

    const int grp = lane >> 3;
    const int lr  = lane & 7;
    const int arow = lane & 15;
    const int asel = lane >> 4;

    for (int kt = 0; kt < NKT; kt++) {
        const int slot = kt % NSTAGE;
        if (kt + 2 < NKT) load_tile(kt + 2, (kt + 2) % NSTAGE);

        const uint32_t As = s_base + slot * STAGE_B;
        const uint32_t Bs = As + A_SLOT_B;

        #pragma unroll
        for (int ks = 0; ks < 4; ks++) {
            uint32_t af[4][4];
            #pragma unroll
            for (int mi = 0; mi < 4; mi++) {
                const int row = wm * 64 + mi * 16 + arow;
                const int kc = ks * 16 + asel * 8;
                ldsm_x4(af[mi][0], af[mi][1], af[mi][2], af[mi][3], As + sw_ab(row, kc));
            }
            uint32_t bf[8][2];
            #pragma unroll
            for (int pair = 0; pair < 4; pair++) {
                uint32_t r0, r1, r2, r3;
                if (!BKN) {
                    const int nrow = wn * 64 + pair * 16 + ((grp >> 1) << 3) + lr;
                    const int kc = ks * 16 + ((grp & 1) << 3);
                    ldsm_x4(r0, r1, r2, r3, Bs + sw_ab(nrow, kc));
                } else {
                    const int krow = ks * 16 + ((grp & 1) << 3) + lr;
                    const int ncol = wn * 64 + pair * 16 + ((grp >> 1) << 3);
                    ldsm_x4_t(r0, r1, r2, r3, Bs + sw_kn(krow, ncol));
                }
                bf[pair * 2][0]     = r0;
                bf[pair * 2][1]     = r1;
                bf[pair * 2 + 1][0] = r2;
                bf[pair * 2 + 1][1] = r3;
            }
            #pragma unroll
            for (int mi = 0; mi < 4; mi++)
                #pragma unroll
                for (int ni = 0; ni < 8; ni++)
                    mma_f16(acc[mi][ni], af[mi], bf[ni]);
        }

        if (kt + 2 < NKT) {
            asm volatile("cp.async.wait_group 1;" ::: "memory");
        } else {
            asm volatile("cp.async.wait_group 0;" ::: "memory");
        }
        __syncthreads();
    }

    // ---------------- epilogue ----------------
    const int r  = lane >> 2;
    const int cl = lane & 3;

    long long ldc, coff;
    if (STAGE == 1) {
        ldc = F3;    coff = ((long long)bz * M1 + m0) * F3 + n0;
    } else if (STAGE == 2) {
        ldc = L_DIM; coff = ((long long)bz * L_DIM + m0) * L_DIM + n0;
    } else if (STAGE == 3) {
        ldc = (long long)N_DIM * E_DIM;
        coff = (long long)h * M1 * E_DIM + ((long long)m0 * N_DIM + nn) * E_DIM + n0;
    } else {
        ldc = E_DIM; coff = (long long)m0 * E_DIM + n0;
    }

    #pragma unroll
    for (int mi = 0; mi < 4; mi++) {
        #pragma unroll
        for (int ni = 0; ni < 8; ni++) {
            const int row = wm * 64 + mi * 16 + r;
            const int col = wn * 64 + ni * 8 + cl * 2;
            const float v00 = acc[mi][ni][0] * alpha + s_bias[col];
            const float v01 = acc[mi][ni][1] * alpha + s_bias[col + 1];
            const float v10 = acc[mi][ni][2] * alpha + s_bias[col];
            const float v11 = acc[mi][ni][3] * alpha + s_bias[col + 1];
            if (CH) {
                __half* C = (__half*)Cout + coff;
                *reinterpret_cast<__half2*>(&C[(long long)row * ldc + col]) =
                    __floats2half2_rn(v00, v01);
                *reinterpret_cast<__half2*>(&C[(long long)(row + 8) * ldc + col]) =
                    __floats2half2_rn(v10, v11);
            } else {
                float* C = (float*)Cout + coff;
                *reinterpret_cast<float2*>(&C[(long long)row * ldc + col])       = make_float2(v00, v01);
                *reinterpret_cast<float2*>(&C[(long long)(row + 8) * ldc + col]) = make_float2(v10, v11);
            }
        }
    }
}

// ------------------------------------------------------------------
// fp32 -> fp16 convert
// ------------------------------------------------------------------
__global__ void __launch_bounds__(256) k_f2h(const float4* __restrict__ in,
                                             __half2* __restrict__ out, long long n4) {
    const long long i = (long long)blockIdx.x * blockDim.x + threadIdx.x;
    if (i < n4) {
        float4 v = in[i];
        out[2 * i]     = __floats2half2_rn(v.x, v.y);
        out[2 * i + 1] = __floats2half2_rn(v.z, v.w);
    }
}

// ------------------------------------------------------------------
// Softmax: fp32 scores -> fp16 probs
// ------------------------------------------------------------------
__global__ void __launch_bounds__(256) k_softmax(const float* __restrict__ S,
                                                 __half* __restrict__ P) {
    __shared__ float red_max[8];
    __shared__ float red_sum[8];
    const long long row = blockIdx.x;
    const float4* p = reinterpret_cast<const float4*>(S + row * (long long)L_DIM);
    const int t = threadIdx.x;
    float4 a = p[t];
    float4 b = p[t + 256];

    float m = fmaxf(fmaxf(fmaxf(a.x, a.y), fmaxf(a.z, a.w)),
                    fmaxf(fmaxf(b.x, b.y), fmaxf(b.z, b.w)));
    #pragma unroll
    for (int o = 16; o; o >>= 1) m = fmaxf(m, __shfl_xor_sync(0xFFFFFFFFu, m, o));
    if ((t & 31) == 0) red_max[t >> 5] = m;
    __syncthreads();
    float mall = red_max[0];
    #pragma unroll
    for (int i = 1; i < 8; i++) mall = fmaxf(mall, red_max[i]);

    a.x = __expf(a.x - mall); a.y = __expf(a.y - mall);
    a.z = __expf(a.z - mall); a.w = __expf(a.w - mall);
    b.x = __expf(b.x - mall); b.y = __expf(b.y - mall);
    b.z = __expf(b.z - mall); b.w = __expf(b.w - mall);

    float sum = a.x + a.y + a.z + a.w + b.x + b.y + b.z + b.w;
    #pragma unroll
    for (int o = 16; o; o >>= 1) sum += __shfl_xor_sync(0xFFFFFFFFu, sum, o);
    if ((t & 31) == 0) red_sum[t >> 5] = sum;
    __syncthreads();
    float stot = 0.f;
    #pragma unroll
    for (int i = 0; i < 8; i++) stot += red_sum[i];
    const float inv = 1.0f / stot;

    __half2* q = reinterpret_cast<__half2*>(P + row * (long long)L_DIM);
    q[2 * t]           = __floats2half2_rn(a.x * inv, a.y * inv);
    q[2 * t + 1]       = __floats2half2_rn(a.z * inv, a.w * inv);
    q[512 + 2 * t]     = __floats2half2_rn(b.x * inv, b.y * inv);
    q[512 + 2 * t + 1] = __floats2half2_rn(b.z * inv, b.w * inv);
}

// ------------------------------------------------------------------
// Host
// ------------------------------------------------------------------
extern "C" void kernel_launch(void* const* d_in, const int* in_sizes, int n_in,
                              void* d_out, int out_size) {
    const float* x    = (const float*)d_in[0];
    const float* Wqkv = (const float*)d_in[1];
    const float* bqkv = (const float*)d_in[2];
    const float* Wo   = (const float*)d_in[3];
    const float* bo   = (const float*)d_in[4];
    float* out = (float*)d_out;

    __half *xh, *wqkvh, *woh, *qkv, *attn, *ctx;
    float* scores;
    cudaGetSymbolAddress((void**)&xh, g_xh);
    cudaGetSymbolAddress((void**)&wqkvh, g_wqkv);
    cudaGetSymbolAddress((void**)&woh, g_wo);
    cudaGetSymbolAddress((void**)&qkv, g_qkv);
    cudaGetSymbolAddress((void**)&scores, g_scores);
    cudaGetSymbolAddress((void**)&attn, g_attn);
    cudaGetSymbolAddress((void**)&ctx, g_ctx);

    static bool attr_done = false;
    if (!attr_done) {
        cudaFuncSetAttribute(gemm_mma<1>, cudaFuncAttributeMaxDynamicSharedMemorySize, SMEM_DYN);
        cudaFuncSetAttribute(gemm_mma<2>, cudaFuncAttributeMaxDynamicSharedMemorySize, SMEM_DYN);
        cudaFuncSetAttribute(gemm_mma<3>, cudaFuncAttributeMaxDynamicSharedMemorySize, SMEM_DYN);
        cudaFuncSetAttribute(gemm_mma<4>, cudaFuncAttributeMaxDynamicSharedMemorySize, SMEM_DYN);
        attr_done = true;
    }

    {
        const long long nx = (long long)M1 * E_DIM / 4;
        const long long nw = (long long)H_DIM * F3 * E_DIM / 4;
        const long long no = (long long)H_DIM * E_DIM * E_DIM / 4;
        k_f2h<<<(unsigned)((nx + 255) / 256), 256>>>((const float4*)x, (__half2*)xh, nx);
        k_f2h<<<(unsigned)((nw + 255) / 256), 256>>>((const float4*)Wqkv, (__half2*)wqkvh, nw);
        k_f2h<<<(unsigned)((no + 255) / 256), 256>>>((const float4*)Wo, (__half2*)woh, no);
    }

    gemm_mma<1><<<dim3(F3 / BN, M1 / BM, H_DIM), NTHR, SMEM_DYN>>>(xh, wqkvh, bqkv, qkv);
    gemm_mma<2><<<dim3(L_DIM / BN, L_DIM / BM, H_DIM * N_DIM), NTHR, SMEM_DYN>>>(qkv, qkv, nullptr, scores);
    k_softmax<<<H_DIM * N_DIM * L_DIM, 256>>>(scores, attn);
    gemm_mma<3><<<dim3(E_DIM / BN, L_DIM / BM, H_DIM * N_DIM), NTHR, SMEM_DYN>>>(attn, qkv, nullptr, ctx);
    gemm_mma<4><<<dim3(E_DIM / BN, M1 / BM, 1), NTHR, SMEM_DYN>>>(ctx, woh, bo, out);
}